// round 10
// baseline (speedup 1.0000x reference)
#include <cuda_runtime.h>
#include <cstdint>

#define Bb   32
#define Tt   2048
#define Hh   256
#define G3   768
#define NVv  18
#define NOo  17
#define CL   4       // CTAs per cluster (one cluster per batch)
#define NT   384     // threads per scan CTA
#define NCTA (Bb * CL)

__device__ float g_hout[Bb * Tt * Hh];   // h states for the head GEMM

// ---------------- helpers ----------------
__device__ __forceinline__ unsigned smem_u32(const void* p) {
    return (unsigned)__cvta_generic_to_shared(p);
}
__device__ __forceinline__ unsigned mapa_u32(unsigned local, int rank) {
    unsigned r;
    asm("mapa.shared::cluster.u32 %0, %1, %2;" : "=r"(r) : "r"(local), "r"(rank));
    return r;
}
__device__ __forceinline__ unsigned long long pack2(float lo, float hi) {
    unsigned long long v;
    asm("mov.b64 %0, {%1, %2};" : "=l"(v) : "f"(lo), "f"(hi));
    return v;
}
__device__ __forceinline__ float2 unpack2(unsigned long long v) {
    float lo, hi;
    asm("mov.b64 {%0, %1}, %2;" : "=f"(lo), "=f"(hi) : "l"(v));
    return make_float2(lo, hi);
}
__device__ __forceinline__ unsigned long long fma2(unsigned long long a,
                                                   unsigned long long b,
                                                   unsigned long long c) {
    unsigned long long d;
    asm("fma.rn.f32x2 %0, %1, %2, %3;" : "=l"(d) : "l"(a), "l"(b), "l"(c));
    return d;
}
__device__ __forceinline__ float fast_sigmoid(float x) {
    float e;
    asm("ex2.approx.f32 %0, %1;" : "=f"(e) : "f"(-1.4426950408889634f * x));
    float r;
    asm("rcp.approx.f32 %0, %1;" : "=f"(r) : "f"(1.0f + e));
    return r;
}
__device__ __forceinline__ float fast_tanh(float x) {
    return fmaf(2.0f, fast_sigmoid(2.0f * x), -1.0f);
}
__device__ __forceinline__ void mbar_arm(unsigned m, unsigned bytes) {
    asm volatile("mbarrier.arrive.expect_tx.shared.b64 _, [%0], %1;"
                 :: "r"(m), "r"(bytes) : "memory");
}
__device__ __forceinline__ void mbar_wait(unsigned m, unsigned par) {
    unsigned done;
    do {
        asm volatile(
            "{\n\t.reg .pred P;\n\t"
            "mbarrier.try_wait.parity.acquire.cluster.shared::cta.b64 P, [%1], %2, 0x989680;\n\t"
            "selp.b32 %0, 1, 0, P;\n\t}"
            : "=r"(done) : "r"(m), "r"(par) : "memory");
    } while (!done);
}

// ---------------- kernel 1: GRU scan (R9 + LDS.128 + b64 epi) ----------------
// 32 clusters x 4 CTAs, one batch per cluster. CTA rank owns 192 gate cols
// { g*256 + 64*rank + j } over full K=256, produces h slice [64r, 64r+64).
// All 384 threads FMA (cp=t0%96 col pair, kq=t0/96 k-quarter); threads 0-31
// inline the epilogue (2 h-columns each) after one __syncthreads.
// Sends at step t: epilogue st.async h(t+1) b64 pairs to hbuf[p^1] of all 4
// ranks, signaling mbar[rank][p] (p = t&1, 256 B expected per source).
// Waits at top of step t (t>=1): thread waits ONLY mbar[kq][(t-1)&1].
__global__ __launch_bounds__(NT, 1) __cluster_dims__(CL, 1, 1)
void scan_kernel(const int* __restrict__ tokens,
                 const float* __restrict__ embed,
                 const float* __restrict__ W_ih,
                 const float* __restrict__ b_ih,
                 const float* __restrict__ W_hh,
                 const float* __restrict__ b_hh,
                 float* __restrict__ betas) {
    __shared__ float G_s[NVv * 192];
    __shared__ float embed_s[NVv * Hh];
    __shared__ int   tok_s[Tt];
    __shared__ __align__(16) float part[4][192];      // [kq][col]
    __shared__ __align__(16) unsigned long long hbuf[2][Hh / 2];  // [phase][128]
    __shared__ float bhh_s[192];
    __shared__ __align__(8) unsigned long long mbar[CL][2];       // [src][phase]

    const int t0    = threadIdx.x;
    const int rank  = blockIdx.x & (CL - 1);
    const int batch = blockIdx.x >> 2;
    const int cp    = t0 % 96;
    const int kq    = t0 / 96;                        // warp-uniform (96 = 3 warps)
    const int c0    = 2 * cp;
    const int C0    = ((c0 >> 6) << 8) + (rank << 6) + (c0 & 63);
    const int C1    = C0 + 1;

    // ---- prologue
    for (int i = t0; i < NVv * Hh; i += NT) embed_s[i] = embed[i];
    for (int i = t0; i < 192; i += NT) {
        int g = i >> 6, j = i & 63;
        bhh_s[i] = b_hh[(g << 8) + (rank << 6) + j];
    }
    for (int i = t0; i < Tt; i += NT) tok_s[i] = tokens[batch * Tt + i];
    if (t0 < Hh / 2) hbuf[0][t0] = 0ULL;              // h0 = 0
    if (t0 == 0) {
        #pragma unroll
        for (int q = 0; q < CL; q++)
            #pragma unroll
            for (int pp = 0; pp < 2; pp++)
                asm volatile("mbarrier.init.shared.b64 [%0], 1;"
                             :: "r"(smem_u32(&mbar[q][pp])) : "memory");
    }
    __syncthreads();

    // ---- G table: G[v][c] = embed[v] . W_ih[:,C] + b_ih[C]
    {
        float acc[9]; int Cg[9]; int vv[9];
        #pragma unroll
        for (int i = 0; i < 9; i++) {
            int e = t0 + i * NT;
            int v = e / 192, c = e - v * 192;
            int C = ((c >> 6) << 8) + (rank << 6) + (c & 63);
            acc[i] = b_ih[C]; Cg[i] = C; vv[i] = v * Hh;
        }
        for (int k = 0; k < Hh; k++) {
            const float* Wk = W_ih + (size_t)k * G3;
            #pragma unroll
            for (int i = 0; i < 9; i++)
                acc[i] = fmaf(embed_s[vv[i] + k], Wk[Cg[i]], acc[i]);
        }
        #pragma unroll
        for (int i = 0; i < 9; i++) {
            int e = t0 + i * NT;
            int v = e / 192, c = e - v * 192;
            G_s[v * 192 + c] = acc[i];
        }
    }

    // ---- W_hh into registers: 2 cols x 64 k (32 f32x2 pairs each)
    unsigned long long w0[32], w1[32];
    {
        const float* Wb = W_hh + (size_t)(kq * 64) * G3;
        #pragma unroll
        for (int kk = 0; kk < 32; kk++) {
            w0[kk] = pack2(Wb[(2 * kk) * G3 + C0], Wb[(2 * kk + 1) * G3 + C0]);
            w1[kk] = pack2(Wb[(2 * kk) * G3 + C1], Wb[(2 * kk + 1) * G3 + C1]);
        }
    }
    // arm both phases of all 4 source mbars (guards h(1) and h(2))
    if (t0 == 0) {
        #pragma unroll
        for (int q = 0; q < CL; q++) {
            mbar_arm(smem_u32(&mbar[q][0]), 256);
            mbar_arm(smem_u32(&mbar[q][1]), 256);
        }
    }
    __syncthreads();
    asm volatile("barrier.cluster.arrive.aligned;" ::: "memory");
    asm volatile("barrier.cluster.wait.aligned;"   ::: "memory");

    // ---- cluster addresses
    const unsigned ref = smem_u32(&hbuf[0][0]);
    unsigned base[CL];
    #pragma unroll
    for (int r2 = 0; r2 < CL; r2++) base[r2] = mapa_u32(ref, r2);
    unsigned hoff[2], moff[2];
    #pragma unroll
    for (int pp = 0; pp < 2; pp++) {
        hoff[pp] = smem_u32(&hbuf[pp][0]) - ref;
        moff[pp] = smem_u32(&mbar[rank][pp]) - ref;   // we signal as source `rank`
    }
    const unsigned mymb0 = smem_u32(&mbar[kq][0]);    // the slice I consume
    const unsigned mymb1 = smem_u32(&mbar[kq][1]);

    const int j0 = 2 * t0;                            // epi cols (valid t0 < 32)
    float* out_beta = betas  + (size_t)(batch * Tt) * Hh + (rank << 6) + j0;
    float* out_h    = g_hout + (size_t)(batch * Tt) * Hh + (rank << 6) + j0;
    const int gidx  = (rank << 6) + j0;
    float hprev0 = 0.0f, hprev1 = 0.0f;

    for (int t = 0; t < Tt; t++) {
        const int pc = t & 1;                         // h(t) lives in hbuf[pc]

        // ---- wait only for MY slice of h(t); re-arm for t+2 (quarter leader)
        if (t > 0) {
            const int ph = (t - 1) & 1;               // mbar phase for h(t)
            const unsigned m = ph ? mymb1 : mymb0;
            mbar_wait(m, ((t - 1) >> 1) & 1);
            if (cp == 0) mbar_arm(m, 256);
        }

        // ---- FMA over my k-quarter (LDS.128 broadcast loads)
        {
            const ulonglong2* hb = (const ulonglong2*)&hbuf[pc][kq << 5];
            unsigned long long acc0 = 0ULL, acc1 = 0ULL;
            #pragma unroll
            for (int q = 0; q < 16; q++) {
                ulonglong2 hv = hb[q];
                acc0 = fma2(w0[2 * q],     hv.x, acc0);
                acc1 = fma2(w1[2 * q],     hv.x, acc1);
                acc0 = fma2(w0[2 * q + 1], hv.y, acc0);
                acc1 = fma2(w1[2 * q + 1], hv.y, acc1);
            }
            float2 a0 = unpack2(acc0), a1 = unpack2(acc1);
            *(float2*)&part[kq][c0] = make_float2(a0.x + a0.y, a1.x + a1.y);
        }
        __syncthreads();

        // ---- inline epilogue: threads 0-31, TWO h-outputs each
        if (t0 < 32) {
            const int tok = tok_s[t];
            const float* Gr = &G_s[tok * 192];
            float2 sr = make_float2(bhh_s[j0], bhh_s[j0 + 1]);
            float2 sz = make_float2(bhh_s[64 + j0], bhh_s[64 + j0 + 1]);
            float2 sn = make_float2(bhh_s[128 + j0], bhh_s[128 + j0 + 1]);
            #pragma unroll
            for (int q = 0; q < 4; q++) {
                float2 pr = *(const float2*)&part[q][j0];
                float2 pz = *(const float2*)&part[q][64 + j0];
                float2 pn = *(const float2*)&part[q][128 + j0];
                sr.x += pr.x; sr.y += pr.y;
                sz.x += pz.x; sz.y += pz.y;
                sn.x += pn.x; sn.y += pn.y;
            }
            float r0 = fast_sigmoid(Gr[j0] + sr.x);
            float r1 = fast_sigmoid(Gr[j0 + 1] + sr.y);
            float z0 = fast_sigmoid(Gr[64 + j0] + sz.x);
            float z1 = fast_sigmoid(Gr[64 + j0 + 1] + sz.y);
            float n0 = fast_tanh(fmaf(r0, sn.x, Gr[128 + j0]));
            float n1 = fast_tanh(fmaf(r1, sn.y, Gr[128 + j0 + 1]));
            float hn0 = fmaf(z0, hprev0 - n0, n0);    // (1-z)n + z h
            float hn1 = fmaf(z1, hprev1 - n1, n1);
            hprev0 = hn0; hprev1 = hn1;

            if (t < Tt - 1) {
                unsigned long long pv = pack2(hn0, hn1);
                const unsigned ho2 = hoff[pc ^ 1] + 4u * gidx;   // 8B aligned
                const unsigned mo2 = moff[pc];                    // phase = t&1
                #pragma unroll
                for (int r2 = 0; r2 < CL; r2++) {
                    asm volatile(
                        "st.async.shared::cluster.mbarrier::complete_tx::bytes.b64 [%0], %1, [%2];"
                        :: "r"(base[r2] + ho2), "l"(pv), "r"(base[r2] + mo2) : "memory");
                }
            }
            *(float2*)(out_beta + (size_t)t * Hh) = make_float2(z0, z1);
            *(float2*)(out_h    + (size_t)t * Hh) = make_float2(hn0, hn1);
        }
    }

    // nothing in flight (last-step sends skipped); hold cluster for safety
    asm volatile("barrier.cluster.arrive.aligned;" ::: "memory");
    asm volatile("barrier.cluster.wait.aligned;"   ::: "memory");
}

// ---------------- kernel 2: head GEMM (R2 original, 43 us) ----------------
__global__ __launch_bounds__(256) void head_kernel(const float* __restrict__ W_head,
                                                   const float* __restrict__ b_head,
                                                   float* __restrict__ logits) {
    __shared__ float w_s[NOo * Hh];   // transposed: w_s[o*H + k]
    __shared__ float b_s[NOo];
    for (int i = threadIdx.x; i < NOo * Hh; i += blockDim.x) {
        int o = i / Hh, k = i - o * Hh;
        w_s[i] = W_head[k * NOo + o];
    }
    if (threadIdx.x < NOo) b_s[threadIdx.x] = b_head[threadIdx.x];
    __syncthreads();

    const int row = blockIdx.x * blockDim.x + threadIdx.x;
    const float4* hr = (const float4*)(g_hout + (size_t)row * Hh);
    float acc[NOo];
    #pragma unroll
    for (int o = 0; o < NOo; o++) acc[o] = b_s[o];
    for (int k4 = 0; k4 < Hh / 4; k4++) {
        float4 hv = hr[k4];
        #pragma unroll
        for (int o = 0; o < NOo; o++) {
            const float4 wv = *(const float4*)&w_s[o * Hh + 4 * k4];
            acc[o] = fmaf(hv.x, wv.x, fmaf(hv.y, wv.y, fmaf(hv.z, wv.z, fmaf(hv.w, wv.w, acc[o]))));
        }
    }
    float* out = logits + (size_t)row * NOo;
    #pragma unroll
    for (int o = 0; o < NOo; o++) out[o] = acc[o];
}

// ---------------- launch ----------------
extern "C" void kernel_launch(void* const* d_in, const int* in_sizes, int n_in,
                              void* d_out, int out_size) {
    const int*   tokens = (const int*)d_in[0];
    const float* embed  = (const float*)d_in[1];
    const float* W_ih   = (const float*)d_in[2];
    const float* W_hh   = (const float*)d_in[3];
    const float* b_ih   = (const float*)d_in[4];
    const float* b_hh   = (const float*)d_in[5];
    const float* W_head = (const float*)d_in[6];
    const float* b_head = (const float*)d_in[7];
    (void)in_sizes; (void)n_in; (void)out_size;

    float* out    = (float*)d_out;
    float* logits = out;                          // [B*T, 17]
    float* betas  = out + (size_t)Bb * Tt * NOo;  // [B*T, 256]

    scan_kernel<<<NCTA, NT>>>(tokens, embed, W_ih, b_ih, W_hh, b_hh, betas);
    head_kernel<<<(Bb * Tt) / 256, 256>>>(W_head, b_head, logits);
}

// round 11
// speedup vs baseline: 1.0563x; 1.0563x over previous
#include <cuda_runtime.h>
#include <cstdint>

#define Bb   32
#define Tt   2048
#define Hh   256
#define G3   768
#define NVv  18
#define NOo  17
#define CL   4       // CTAs per cluster (one cluster per batch)
#define NT   384     // threads per scan CTA
#define NCTA (Bb * CL)

__device__ float g_hout[Bb * Tt * Hh];   // h states for the head GEMM

// ---------------- helpers ----------------
__device__ __forceinline__ unsigned smem_u32(const void* p) {
    return (unsigned)__cvta_generic_to_shared(p);
}
__device__ __forceinline__ unsigned mapa_u32(unsigned local, int rank) {
    unsigned r;
    asm("mapa.shared::cluster.u32 %0, %1, %2;" : "=r"(r) : "r"(local), "r"(rank));
    return r;
}
__device__ __forceinline__ unsigned long long pack2(float lo, float hi) {
    unsigned long long v;
    asm("mov.b64 %0, {%1, %2};" : "=l"(v) : "f"(lo), "f"(hi));
    return v;
}
__device__ __forceinline__ float2 unpack2(unsigned long long v) {
    float lo, hi;
    asm("mov.b64 {%0, %1}, %2;" : "=f"(lo), "=f"(hi) : "l"(v));
    return make_float2(lo, hi);
}
__device__ __forceinline__ unsigned long long fma2(unsigned long long a,
                                                   unsigned long long b,
                                                   unsigned long long c) {
    unsigned long long d;
    asm("fma.rn.f32x2 %0, %1, %2, %3;" : "=l"(d) : "l"(a), "l"(b), "l"(c));
    return d;
}
__device__ __forceinline__ float fast_sigmoid(float x) {
    float e;
    asm("ex2.approx.f32 %0, %1;" : "=f"(e) : "f"(-1.4426950408889634f * x));
    float r;
    asm("rcp.approx.f32 %0, %1;" : "=f"(r) : "f"(1.0f + e));
    return r;
}
__device__ __forceinline__ float fast_tanh(float x) {
    return fmaf(2.0f, fast_sigmoid(2.0f * x), -1.0f);
}
__device__ __forceinline__ void mbar_arm(unsigned m, unsigned bytes) {
    asm volatile("mbarrier.arrive.expect_tx.shared.b64 _, [%0], %1;"
                 :: "r"(m), "r"(bytes) : "memory");
}
__device__ __forceinline__ void mbar_wait(unsigned m, unsigned par) {
    unsigned done;
    do {
        asm volatile(
            "{\n\t.reg .pred P;\n\t"
            "mbarrier.try_wait.parity.acquire.cluster.shared::cta.b64 P, [%1], %2, 0x989680;\n\t"
            "selp.b32 %0, 1, 0, P;\n\t}"
            : "=r"(done) : "r"(m), "r"(par) : "memory");
    } while (!done);
}

// ---------------- kernel 1: GRU scan (R9 + LDS.128 FMA loads ONLY) ----------------
// 32 clusters x 4 CTAs, one batch per cluster. CTA rank owns 192 gate cols
// { g*256 + 64*rank + j } over full K=256, produces h slice [64r, 64r+64).
// All 384 threads FMA (cp=t0%96 col pair, kq=t0/96 k-quarter); threads 0-63
// inline the epilogue after one __syncthreads (identical to R9).
// Sends at step t: epilogue st.async h(t+1) b32 to hbuf[p^1] of all 4 ranks,
// signaling mbar[rank][p] (p = t&1, 256 B expected per source).
// Waits at top of step t (t>=1): thread waits ONLY mbar[kq][(t-1)&1].
__global__ __launch_bounds__(NT, 1) __cluster_dims__(CL, 1, 1)
void scan_kernel(const int* __restrict__ tokens,
                 const float* __restrict__ embed,
                 const float* __restrict__ W_ih,
                 const float* __restrict__ b_ih,
                 const float* __restrict__ W_hh,
                 const float* __restrict__ b_hh,
                 float* __restrict__ betas) {
    __shared__ float G_s[NVv * 192];
    __shared__ float embed_s[NVv * Hh];
    __shared__ int   tok_s[Tt];
    __shared__ __align__(16) float part[4][192];      // [kq][col]
    __shared__ __align__(16) unsigned long long hbuf[2][Hh / 2];  // [phase][128]
    __shared__ float bhh_s[192];
    __shared__ __align__(8) unsigned long long mbar[CL][2];       // [src][phase]

    const int t0    = threadIdx.x;
    const int rank  = blockIdx.x & (CL - 1);
    const int batch = blockIdx.x >> 2;
    const int cp    = t0 % 96;
    const int kq    = t0 / 96;                        // warp-uniform (96 = 3 warps)
    const int c0    = 2 * cp;
    const int C0    = ((c0 >> 6) << 8) + (rank << 6) + (c0 & 63);
    const int C1    = C0 + 1;

    // ---- prologue
    for (int i = t0; i < NVv * Hh; i += NT) embed_s[i] = embed[i];
    for (int i = t0; i < 192; i += NT) {
        int g = i >> 6, j = i & 63;
        bhh_s[i] = b_hh[(g << 8) + (rank << 6) + j];
    }
    for (int i = t0; i < Tt; i += NT) tok_s[i] = tokens[batch * Tt + i];
    if (t0 < Hh / 2) hbuf[0][t0] = 0ULL;              // h0 = 0
    if (t0 == 0) {
        #pragma unroll
        for (int q = 0; q < CL; q++)
            #pragma unroll
            for (int pp = 0; pp < 2; pp++)
                asm volatile("mbarrier.init.shared.b64 [%0], 1;"
                             :: "r"(smem_u32(&mbar[q][pp])) : "memory");
    }
    __syncthreads();

    // ---- G table: G[v][c] = embed[v] . W_ih[:,C] + b_ih[C]
    {
        float acc[9]; int Cg[9]; int vv[9];
        #pragma unroll
        for (int i = 0; i < 9; i++) {
            int e = t0 + i * NT;
            int v = e / 192, c = e - v * 192;
            int C = ((c >> 6) << 8) + (rank << 6) + (c & 63);
            acc[i] = b_ih[C]; Cg[i] = C; vv[i] = v * Hh;
        }
        for (int k = 0; k < Hh; k++) {
            const float* Wk = W_ih + (size_t)k * G3;
            #pragma unroll
            for (int i = 0; i < 9; i++)
                acc[i] = fmaf(embed_s[vv[i] + k], Wk[Cg[i]], acc[i]);
        }
        #pragma unroll
        for (int i = 0; i < 9; i++) {
            int e = t0 + i * NT;
            int v = e / 192, c = e - v * 192;
            G_s[v * 192 + c] = acc[i];
        }
    }

    // ---- W_hh into registers: 2 cols x 64 k (32 f32x2 pairs each)
    unsigned long long w0[32], w1[32];
    {
        const float* Wb = W_hh + (size_t)(kq * 64) * G3;
        #pragma unroll
        for (int kk = 0; kk < 32; kk++) {
            w0[kk] = pack2(Wb[(2 * kk) * G3 + C0], Wb[(2 * kk + 1) * G3 + C0]);
            w1[kk] = pack2(Wb[(2 * kk) * G3 + C1], Wb[(2 * kk + 1) * G3 + C1]);
        }
    }
    // arm both phases of all 4 source mbars (guards h(1) and h(2))
    if (t0 == 0) {
        #pragma unroll
        for (int q = 0; q < CL; q++) {
            mbar_arm(smem_u32(&mbar[q][0]), 256);
            mbar_arm(smem_u32(&mbar[q][1]), 256);
        }
    }
    __syncthreads();
    asm volatile("barrier.cluster.arrive.aligned;" ::: "memory");
    asm volatile("barrier.cluster.wait.aligned;"   ::: "memory");

    // ---- cluster addresses
    const unsigned ref = smem_u32(&hbuf[0][0]);
    unsigned base[CL];
    #pragma unroll
    for (int r2 = 0; r2 < CL; r2++) base[r2] = mapa_u32(ref, r2);
    unsigned hoff[2], moff[2];
    #pragma unroll
    for (int pp = 0; pp < 2; pp++) {
        hoff[pp] = smem_u32(&hbuf[pp][0]) - ref;
        moff[pp] = smem_u32(&mbar[rank][pp]) - ref;   // we signal as source `rank`
    }
    const unsigned mymb0 = smem_u32(&mbar[kq][0]);    // the slice I consume
    const unsigned mymb1 = smem_u32(&mbar[kq][1]);

    float* out_beta = betas  + (size_t)(batch * Tt) * Hh + (rank << 6);
    float* out_h    = g_hout + (size_t)(batch * Tt) * Hh + (rank << 6);
    const int gidx  = (rank << 6) + t0;               // valid for t0 < 64
    float hprev = 0.0f;

    for (int t = 0; t < Tt; t++) {
        const int pc = t & 1;                         // h(t) lives in hbuf[pc]

        // ---- wait only for MY slice of h(t); re-arm for t+2 (quarter leader)
        if (t > 0) {
            const int ph = (t - 1) & 1;               // mbar phase for h(t)
            const unsigned m = ph ? mymb1 : mymb0;
            mbar_wait(m, ((t - 1) >> 1) & 1);
            if (cp == 0) mbar_arm(m, 256);
        }

        // ---- FMA over my k-quarter (LDS.128 broadcast loads — ONLY change vs R9)
        {
            const ulonglong2* hb = (const ulonglong2*)&hbuf[pc][kq << 5];
            unsigned long long acc0 = 0ULL, acc1 = 0ULL;
            #pragma unroll
            for (int q = 0; q < 16; q++) {
                ulonglong2 hv = hb[q];
                acc0 = fma2(w0[2 * q],     hv.x, acc0);
                acc1 = fma2(w1[2 * q],     hv.x, acc1);
                acc0 = fma2(w0[2 * q + 1], hv.y, acc0);
                acc1 = fma2(w1[2 * q + 1], hv.y, acc1);
            }
            float2 a0 = unpack2(acc0), a1 = unpack2(acc1);
            *(float2*)&part[kq][c0] = make_float2(a0.x + a0.y, a1.x + a1.y);
        }
        __syncthreads();

        // ---- inline epilogue: threads 0-63, one h-output each (R9-identical)
        if (t0 < 64) {
            const int j = t0;
            const int tok = tok_s[t];
            const float* Gr = &G_s[tok * 192];
            float sr = (part[0][j] + part[1][j]) + (part[2][j] + part[3][j]) + bhh_s[j];
            float sz = (part[0][64 + j] + part[1][64 + j]) + (part[2][64 + j] + part[3][64 + j]) + bhh_s[64 + j];
            float sn = (part[0][128 + j] + part[1][128 + j]) + (part[2][128 + j] + part[3][128 + j]) + bhh_s[128 + j];
            float r  = fast_sigmoid(Gr[j] + sr);
            float z  = fast_sigmoid(Gr[64 + j] + sz);
            float n  = fast_tanh(fmaf(r, sn, Gr[128 + j]));
            float hn = fmaf(z, hprev - n, n);         // (1-z)n + z h
            hprev = hn;

            if (t < Tt - 1) {
                const unsigned ho2 = hoff[pc ^ 1] + 4u * gidx;   // h(t+1) buffer
                const unsigned mo2 = moff[pc];                    // phase = t&1
                #pragma unroll
                for (int r2 = 0; r2 < CL; r2++) {
                    asm volatile(
                        "st.async.shared::cluster.mbarrier::complete_tx::bytes.b32 [%0], %1, [%2];"
                        :: "r"(base[r2] + ho2), "f"(hn), "r"(base[r2] + mo2) : "memory");
                }
            }
            out_beta[(size_t)t * Hh + j] = z;
            out_h[(size_t)t * Hh + j]    = hn;
        }
    }

    // nothing in flight (last-step sends skipped); hold cluster for safety
    asm volatile("barrier.cluster.arrive.aligned;" ::: "memory");
    asm volatile("barrier.cluster.wait.aligned;"   ::: "memory");
}

// ---------------- kernel 2: head GEMM (R2 original, 43 us) ----------------
__global__ __launch_bounds__(256) void head_kernel(const float* __restrict__ W_head,
                                                   const float* __restrict__ b_head,
                                                   float* __restrict__ logits) {
    __shared__ float w_s[NOo * Hh];   // transposed: w_s[o*H + k]
    __shared__ float b_s[NOo];
    for (int i = threadIdx.x; i < NOo * Hh; i += blockDim.x) {
        int o = i / Hh, k = i - o * Hh;
        w_s[i] = W_head[k * NOo + o];
    }
    if (threadIdx.x < NOo) b_s[threadIdx.x] = b_head[threadIdx.x];
    __syncthreads();

    const int row = blockIdx.x * blockDim.x + threadIdx.x;
    const float4* hr = (const float4*)(g_hout + (size_t)row * Hh);
    float acc[NOo];
    #pragma unroll
    for (int o = 0; o < NOo; o++) acc[o] = b_s[o];
    for (int k4 = 0; k4 < Hh / 4; k4++) {
        float4 hv = hr[k4];
        #pragma unroll
        for (int o = 0; o < NOo; o++) {
            const float4 wv = *(const float4*)&w_s[o * Hh + 4 * k4];
            acc[o] = fmaf(hv.x, wv.x, fmaf(hv.y, wv.y, fmaf(hv.z, wv.z, fmaf(hv.w, wv.w, acc[o]))));
        }
    }
    float* out = logits + (size_t)row * NOo;
    #pragma unroll
    for (int o = 0; o < NOo; o++) out[o] = acc[o];
}

// ---------------- launch ----------------
extern "C" void kernel_launch(void* const* d_in, const int* in_sizes, int n_in,
                              void* d_out, int out_size) {
    const int*   tokens = (const int*)d_in[0];
    const float* embed  = (const float*)d_in[1];
    const float* W_ih   = (const float*)d_in[2];
    const float* W_hh   = (const float*)d_in[3];
    const float* b_ih   = (const float*)d_in[4];
    const float* b_hh   = (const float*)d_in[5];
    const float* W_head = (const float*)d_in[6];
    const float* b_head = (const float*)d_in[7];
    (void)in_sizes; (void)n_in; (void)out_size;

    float* out    = (float*)d_out;
    float* logits = out;                          // [B*T, 17]
    float* betas  = out + (size_t)Bb * Tt * NOo;  // [B*T, 256]

    scan_kernel<<<NCTA, NT>>>(tokens, embed, W_ih, b_ih, W_hh, b_hh, betas);
    head_kernel<<<(Bb * Tt) / 256, 256>>>(W_head, b_head, logits);
}

// round 12
// speedup vs baseline: 1.1561x; 1.0945x over previous
#include <cuda_runtime.h>
#include <cstdint>

#define Bb   32
#define Tt   2048
#define Hh   256
#define G3   768
#define NVv  18
#define NOo  17
#define CL   4       // CTAs per cluster (one cluster per batch)
#define NT   384     // threads per scan CTA
#define NCTA (Bb * CL)

__device__ float g_hout[Bb * Tt * Hh];   // h states for the head GEMM

// ---------------- helpers ----------------
__device__ __forceinline__ unsigned smem_u32(const void* p) {
    return (unsigned)__cvta_generic_to_shared(p);
}
__device__ __forceinline__ unsigned mapa_u32(unsigned local, int rank) {
    unsigned r;
    asm("mapa.shared::cluster.u32 %0, %1, %2;" : "=r"(r) : "r"(local), "r"(rank));
    return r;
}
__device__ __forceinline__ unsigned long long pack2(float lo, float hi) {
    unsigned long long v;
    asm("mov.b64 %0, {%1, %2};" : "=l"(v) : "f"(lo), "f"(hi));
    return v;
}
__device__ __forceinline__ float2 unpack2(unsigned long long v) {
    float lo, hi;
    asm("mov.b64 {%0, %1}, %2;" : "=f"(lo), "=f"(hi) : "l"(v));
    return make_float2(lo, hi);
}
__device__ __forceinline__ unsigned long long fma2(unsigned long long a,
                                                   unsigned long long b,
                                                   unsigned long long c) {
    unsigned long long d;
    asm("fma.rn.f32x2 %0, %1, %2, %3;" : "=l"(d) : "l"(a), "l"(b), "l"(c));
    return d;
}
// single-MUFU activations (sm_75+ tanh.approx.f32)
__device__ __forceinline__ float fast_tanh(float x) {
    float y;
    asm("tanh.approx.f32 %0, %1;" : "=f"(y) : "f"(x));
    return y;
}
__device__ __forceinline__ float fast_sigmoid(float x) {
    return fmaf(0.5f, fast_tanh(0.5f * x), 0.5f);
}
__device__ __forceinline__ void mbar_arm(unsigned m, unsigned bytes) {
    asm volatile("mbarrier.arrive.expect_tx.shared.b64 _, [%0], %1;"
                 :: "r"(m), "r"(bytes) : "memory");
}
__device__ __forceinline__ void mbar_wait(unsigned m, unsigned par) {
    unsigned done;
    do {
        asm volatile(
            "{\n\t.reg .pred P;\n\t"
            "mbarrier.try_wait.parity.acquire.cluster.shared::cta.b64 P, [%1], %2, 0x989680;\n\t"
            "selp.b32 %0, 1, 0, P;\n\t}"
            : "=r"(done) : "r"(m), "r"(par) : "memory");
    } while (!done);
}

// ---------------- kernel 1: GRU scan (R11 + tanh.approx epilogue) ----------------
// 32 clusters x 4 CTAs, one batch per cluster. CTA rank owns 192 gate cols
// { g*256 + 64*rank + j } over full K=256, produces h slice [64r, 64r+64).
// All 384 threads FMA (cp=t0%96 col pair, kq=t0/96 k-quarter); threads 0-63
// inline the epilogue after one __syncthreads.
// Sends at step t: epilogue st.async h(t+1) b32 to hbuf[p^1] of all 4 ranks
// (remote ranks first), signaling mbar[rank][p] (p = t&1, 256 B per source).
// Waits at top of step t (t>=1): thread waits ONLY mbar[kq][(t-1)&1].
__global__ __launch_bounds__(NT, 1) __cluster_dims__(CL, 1, 1)
void scan_kernel(const int* __restrict__ tokens,
                 const float* __restrict__ embed,
                 const float* __restrict__ W_ih,
                 const float* __restrict__ b_ih,
                 const float* __restrict__ W_hh,
                 const float* __restrict__ b_hh,
                 float* __restrict__ betas) {
    __shared__ float G_s[NVv * 192];
    __shared__ float embed_s[NVv * Hh];
    __shared__ int   tok_s[Tt];
    __shared__ __align__(16) float part[4][192];      // [kq][col]
    __shared__ __align__(16) unsigned long long hbuf[2][Hh / 2];  // [phase][128]
    __shared__ float bhh_s[192];
    __shared__ __align__(8) unsigned long long mbar[CL][2];       // [src][phase]

    const int t0    = threadIdx.x;
    const int rank  = blockIdx.x & (CL - 1);
    const int batch = blockIdx.x >> 2;
    const int cp    = t0 % 96;
    const int kq    = t0 / 96;                        // warp-uniform (96 = 3 warps)
    const int c0    = 2 * cp;
    const int C0    = ((c0 >> 6) << 8) + (rank << 6) + (c0 & 63);
    const int C1    = C0 + 1;

    // ---- prologue
    for (int i = t0; i < NVv * Hh; i += NT) embed_s[i] = embed[i];
    for (int i = t0; i < 192; i += NT) {
        int g = i >> 6, j = i & 63;
        bhh_s[i] = b_hh[(g << 8) + (rank << 6) + j];
    }
    for (int i = t0; i < Tt; i += NT) tok_s[i] = tokens[batch * Tt + i];
    if (t0 < Hh / 2) hbuf[0][t0] = 0ULL;              // h0 = 0
    if (t0 == 0) {
        #pragma unroll
        for (int q = 0; q < CL; q++)
            #pragma unroll
            for (int pp = 0; pp < 2; pp++)
                asm volatile("mbarrier.init.shared.b64 [%0], 1;"
                             :: "r"(smem_u32(&mbar[q][pp])) : "memory");
    }
    __syncthreads();

    // ---- G table: G[v][c] = embed[v] . W_ih[:,C] + b_ih[C]
    {
        float acc[9]; int Cg[9]; int vv[9];
        #pragma unroll
        for (int i = 0; i < 9; i++) {
            int e = t0 + i * NT;
            int v = e / 192, c = e - v * 192;
            int C = ((c >> 6) << 8) + (rank << 6) + (c & 63);
            acc[i] = b_ih[C]; Cg[i] = C; vv[i] = v * Hh;
        }
        for (int k = 0; k < Hh; k++) {
            const float* Wk = W_ih + (size_t)k * G3;
            #pragma unroll
            for (int i = 0; i < 9; i++)
                acc[i] = fmaf(embed_s[vv[i] + k], Wk[Cg[i]], acc[i]);
        }
        #pragma unroll
        for (int i = 0; i < 9; i++) {
            int e = t0 + i * NT;
            int v = e / 192, c = e - v * 192;
            G_s[v * 192 + c] = acc[i];
        }
    }

    // ---- W_hh into registers: 2 cols x 64 k (32 f32x2 pairs each)
    unsigned long long w0[32], w1[32];
    {
        const float* Wb = W_hh + (size_t)(kq * 64) * G3;
        #pragma unroll
        for (int kk = 0; kk < 32; kk++) {
            w0[kk] = pack2(Wb[(2 * kk) * G3 + C0], Wb[(2 * kk + 1) * G3 + C0]);
            w1[kk] = pack2(Wb[(2 * kk) * G3 + C1], Wb[(2 * kk + 1) * G3 + C1]);
        }
    }
    // arm both phases of all 4 source mbars (guards h(1) and h(2))
    if (t0 == 0) {
        #pragma unroll
        for (int q = 0; q < CL; q++) {
            mbar_arm(smem_u32(&mbar[q][0]), 256);
            mbar_arm(smem_u32(&mbar[q][1]), 256);
        }
    }
    __syncthreads();
    asm volatile("barrier.cluster.arrive.aligned;" ::: "memory");
    asm volatile("barrier.cluster.wait.aligned;"   ::: "memory");

    // ---- cluster addresses
    const unsigned ref = smem_u32(&hbuf[0][0]);
    unsigned base[CL];
    #pragma unroll
    for (int r2 = 0; r2 < CL; r2++) base[r2] = mapa_u32(ref, r2);
    unsigned hoff[2], moff[2];
    #pragma unroll
    for (int pp = 0; pp < 2; pp++) {
        hoff[pp] = smem_u32(&hbuf[pp][0]) - ref;
        moff[pp] = smem_u32(&mbar[rank][pp]) - ref;   // we signal as source `rank`
    }
    const unsigned mymb0 = smem_u32(&mbar[kq][0]);    // the slice I consume
    const unsigned mymb1 = smem_u32(&mbar[kq][1]);

    float* out_beta = betas  + (size_t)(batch * Tt) * Hh + (rank << 6);
    float* out_h    = g_hout + (size_t)(batch * Tt) * Hh + (rank << 6);
    const int gidx  = (rank << 6) + t0;               // valid for t0 < 64
    float hprev = 0.0f;

    for (int t = 0; t < Tt; t++) {
        const int pc = t & 1;                         // h(t) lives in hbuf[pc]

        // ---- wait only for MY slice of h(t); re-arm for t+2 (quarter leader)
        if (t > 0) {
            const int ph = (t - 1) & 1;               // mbar phase for h(t)
            const unsigned m = ph ? mymb1 : mymb0;
            mbar_wait(m, ((t - 1) >> 1) & 1);
            if (cp == 0) mbar_arm(m, 256);
        }

        // ---- FMA over my k-quarter (LDS.128 broadcast loads)
        {
            const ulonglong2* hb = (const ulonglong2*)&hbuf[pc][kq << 5];
            unsigned long long acc0 = 0ULL, acc1 = 0ULL;
            #pragma unroll
            for (int q = 0; q < 16; q++) {
                ulonglong2 hv = hb[q];
                acc0 = fma2(w0[2 * q],     hv.x, acc0);
                acc1 = fma2(w1[2 * q],     hv.x, acc1);
                acc0 = fma2(w0[2 * q + 1], hv.y, acc0);
                acc1 = fma2(w1[2 * q + 1], hv.y, acc1);
            }
            float2 a0 = unpack2(acc0), a1 = unpack2(acc1);
            *(float2*)&part[kq][c0] = make_float2(a0.x + a0.y, a1.x + a1.y);
        }
        __syncthreads();

        // ---- inline epilogue: threads 0-63, one h-output each
        if (t0 < 64) {
            const int j = t0;
            const int tok = tok_s[t];
            const float* Gr = &G_s[tok * 192];
            float sr = (part[0][j] + part[1][j]) + (part[2][j] + part[3][j]) + bhh_s[j];
            float sz = (part[0][64 + j] + part[1][64 + j]) + (part[2][64 + j] + part[3][64 + j]) + bhh_s[64 + j];
            float sn = (part[0][128 + j] + part[1][128 + j]) + (part[2][128 + j] + part[3][128 + j]) + bhh_s[128 + j];
            float r  = fast_sigmoid(Gr[j] + sr);
            float z  = fast_sigmoid(Gr[64 + j] + sz);
            float n  = fast_tanh(fmaf(r, sn, Gr[128 + j]));
            float hn = fmaf(z, hprev - n, n);         // (1-z)n + z h
            hprev = hn;

            if (t < Tt - 1) {
                const unsigned ho2 = hoff[pc ^ 1] + 4u * gidx;   // h(t+1) buffer
                const unsigned mo2 = moff[pc];                    // phase = t&1
                // remote ranks first so DSMEM delivery starts earliest
                #pragma unroll
                for (int d = 1; d <= CL; d++) {
                    const int r2 = (rank + d) & (CL - 1);
                    asm volatile(
                        "st.async.shared::cluster.mbarrier::complete_tx::bytes.b32 [%0], %1, [%2];"
                        :: "r"(base[r2] + ho2), "f"(hn), "r"(base[r2] + mo2) : "memory");
                }
            }
            out_beta[(size_t)t * Hh + j] = z;
            out_h[(size_t)t * Hh + j]    = hn;
        }
    }

    // nothing in flight (last-step sends skipped); hold cluster for safety
    asm volatile("barrier.cluster.arrive.aligned;" ::: "memory");
    asm volatile("barrier.cluster.wait.aligned;"   ::: "memory");
}

// ---------------- kernel 2: head GEMM (R2 original, 43 us) ----------------
__global__ __launch_bounds__(256) void head_kernel(const float* __restrict__ W_head,
                                                   const float* __restrict__ b_head,
                                                   float* __restrict__ logits) {
    __shared__ float w_s[NOo * Hh];   // transposed: w_s[o*H + k]
    __shared__ float b_s[NOo];
    for (int i = threadIdx.x; i < NOo * Hh; i += blockDim.x) {
        int o = i / Hh, k = i - o * Hh;
        w_s[i] = W_head[k * NOo + o];
    }
    if (threadIdx.x < NOo) b_s[threadIdx.x] = b_head[threadIdx.x];
    __syncthreads();

    const int row = blockIdx.x * blockDim.x + threadIdx.x;
    const float4* hr = (const float4*)(g_hout + (size_t)row * Hh);
    float acc[NOo];
    #pragma unroll
    for (int o = 0; o < NOo; o++) acc[o] = b_s[o];
    for (int k4 = 0; k4 < Hh / 4; k4++) {
        float4 hv = hr[k4];
        #pragma unroll
        for (int o = 0; o < NOo; o++) {
            const float4 wv = *(const float4*)&w_s[o * Hh + 4 * k4];
            acc[o] = fmaf(hv.x, wv.x, fmaf(hv.y, wv.y, fmaf(hv.z, wv.z, fmaf(hv.w, wv.w, acc[o]))));
        }
    }
    float* out = logits + (size_t)row * NOo;
    #pragma unroll
    for (int o = 0; o < NOo; o++) out[o] = acc[o];
}

// ---------------- launch ----------------
extern "C" void kernel_launch(void* const* d_in, const int* in_sizes, int n_in,
                              void* d_out, int out_size) {
    const int*   tokens = (const int*)d_in[0];
    const float* embed  = (const float*)d_in[1];
    const float* W_ih   = (const float*)d_in[2];
    const float* W_hh   = (const float*)d_in[3];
    const float* b_ih   = (const float*)d_in[4];
    const float* b_hh   = (const float*)d_in[5];
    const float* W_head = (const float*)d_in[6];
    const float* b_head = (const float*)d_in[7];
    (void)in_sizes; (void)n_in; (void)out_size;

    float* out    = (float*)d_out;
    float* logits = out;                          // [B*T, 17]
    float* betas  = out + (size_t)Bb * Tt * NOo;  // [B*T, 256]

    scan_kernel<<<NCTA, NT>>>(tokens, embed, W_ih, b_ih, W_hh, b_hh, betas);
    head_kernel<<<(Bb * Tt) / 256, 256>>>(W_head, b_head, logits);
}